// round 14
// baseline (speedup 1.0000x reference)
#include <cuda_runtime.h>

// shift op: x[32, 288, 64, 64] f32, NCHW. cpg = 32.
// group g in 0..7: out[:, g*32+(0..31), h, w] = x[same ch, h+dh, w+dw] (0 outside)
// group 8 (c in [256,288)): zeros.
//
// FINAL (converged at the HBM roofline): 285 MB compulsory traffic at
// ~6.26 TB/s sustained combined R/W = ~45.5-46.4 us. Search tree closed
// with measurements across 13 rounds:
//  - SM-side levers (ILP/MLP 1-8, occupancy 49-80%, 32/128/256-bit access,
//    L2 load policies default/nc/evict_last, store policies default/.cs,
//    burst depth, block shape): all flat within run noise.
//  - Kernel + memset-node decomposition of the zero group: 82 us regression
//    (graph node overhead dominates); single fused kernel is optimal.
//  - Traffic-normalized rate is shape-invariant (7.24-7.37 MB/us for both
//    8192- and 9216-block variants): no wave/scheduling slack remains.
// Residual 27% DRAM idle is bus read/write turnaround, not addressable
// from the SM side.
//
//   One block = one (b,c) plane (64x64). 256 threads, each thread handles 4
//   aligned float4 quads at rows {r, r+16, r+32, r+48}. dw=+/-1 quads are
//   rebuilt from the aligned quad + one lane-shuffled element, so every
//   global load is an aligned LDG.128 and each input byte is read exactly
//   once. Streaming (.cs) policy on both loads and stores.

#define SH_H 64
#define SH_W 64
#define SH_C 288

__constant__ int c_dh[8] = {-1,  1,  0,  0, -1, -1,  1,  1};
__constant__ int c_dw[8] = { 0,  0, -1,  1, -1,  1, -1,  1};

__global__ __launch_bounds__(256) void shift_kernel(const float* __restrict__ x,
                                                    float* __restrict__ out) {
    const int tid   = threadIdx.x;
    const int wq    = tid & 15;        // quad index within row (0..15)
    const int rbase = tid >> 4;        // 0..15; rows rbase + {0,16,32,48}

    const int bc = blockIdx.x;         // fused (b, c) plane index
    const int c  = bc - (bc / SH_C) * SH_C;
    const int g  = c >> 5;             // cpg = 32

    const long plane = (long)bc * (SH_H * SH_W);
    float4* __restrict__ dstp = reinterpret_cast<float4*>(out + plane) + wq;

    const float4 zero = make_float4(0.f, 0.f, 0.f, 0.f);

    if (g >= 8) {                      // zero group (channels 256..287)
#pragma unroll
        for (int i = 0; i < 4; ++i) {
            const int h = rbase + (i << 4);
            __stcs(dstp + h * (SH_W / 4), zero);
        }
        return;
    }

    const int dh = c_dh[g];
    const int dw = c_dw[g];

    const float4* __restrict__ srcp = reinterpret_cast<const float4*>(x + plane) + wq;

    // Issue all 4 aligned loads first (MLP=4). OOB source rows -> zero quad.
    float4 q[4];
#pragma unroll
    for (int i = 0; i < 4; ++i) {
        const int hs = rbase + (i << 4) + dh;
        q[i] = ((unsigned)hs < SH_H) ? __ldcs(srcp + hs * (SH_W / 4)) : zero;
    }

    if (dw == 0) {
#pragma unroll
        for (int i = 0; i < 4; ++i) {
            const int h = rbase + (i << 4);
            __stcs(dstp + h * (SH_W / 4), q[i]);
        }
    } else if (dw > 0) {
        // out quad = {q.y, q.z, q.w, next_lane.q.x}; wq==15 -> last elem = 0
#pragma unroll
        for (int i = 0; i < 4; ++i) {
            float nx = __shfl_down_sync(0xffffffffu, q[i].x, 1);
            if (wq == 15) nx = 0.f;
            const int h = rbase + (i << 4);
            __stcs(dstp + h * (SH_W / 4), make_float4(q[i].y, q[i].z, q[i].w, nx));
        }
    } else {
        // out quad = {prev_lane.q.w, q.x, q.y, q.z}; wq==0 -> first elem = 0
#pragma unroll
        for (int i = 0; i < 4; ++i) {
            float pw = __shfl_up_sync(0xffffffffu, q[i].w, 1);
            if (wq == 0) pw = 0.f;
            const int h = rbase + (i << 4);
            __stcs(dstp + h * (SH_W / 4), make_float4(pw, q[i].x, q[i].y, q[i].z));
        }
    }
}

extern "C" void kernel_launch(void* const* d_in, const int* in_sizes, int n_in,
                              void* d_out, int out_size) {
    const float* x = (const float*)d_in[0];
    float* out = (float*)d_out;
    const int grid = 32 * SH_C;   // one block per (b, c) plane
    shift_kernel<<<grid, 256>>>(x, out);
}

// round 15
// speedup vs baseline: 1.0295x; 1.0295x over previous
#include <cuda_runtime.h>

// shift op: x[32, 288, 64, 64] f32, NCHW. cpg = 32.
// group g in 0..7: out[:, g*32+(0..31), h, w] = x[same ch, h+dh, w+dw] (0 outside)
// group 8 (c in [256,288)): zeros.
//
// FINAL (converged at the HBM roofline): 285 MB compulsory traffic at
// ~6.2 TB/s sustained combined R/W = 45.5-46.9 us (7 runs of this exact
// source; spread is bench noise, profile byte-stable). Search tree closed
// across 14 rounds:
//  - SM-side levers (ILP/MLP 1-8, occupancy 49-80%, 32/128/256-bit access,
//    L2 load policies default/nc/evict_last, store policies default/.cs,
//    burst depth, block shape): all flat within run noise.
//  - Kernel + memset-node decomposition of the zero group: 82 us regression
//    (graph node overhead dominates); single fused kernel is optimal.
//  - Traffic-normalized rate is shape-invariant (7.24-7.37 MB/us across all
//    grids/shapes): no wave/scheduling slack remains.
// Residual ~27% DRAM idle is bus read/write turnaround, not addressable
// from the SM side.
//
//   One block = one (b,c) plane (64x64). 256 threads, each thread handles 4
//   aligned float4 quads at rows {r, r+16, r+32, r+48}. dw=+/-1 quads are
//   rebuilt from the aligned quad + one lane-shuffled element, so every
//   global load is an aligned LDG.128 and each input byte is read exactly
//   once. Streaming (.cs) policy on both loads and stores.

#define SH_H 64
#define SH_W 64
#define SH_C 288

__constant__ int c_dh[8] = {-1,  1,  0,  0, -1, -1,  1,  1};
__constant__ int c_dw[8] = { 0,  0, -1,  1, -1,  1, -1,  1};

__global__ __launch_bounds__(256) void shift_kernel(const float* __restrict__ x,
                                                    float* __restrict__ out) {
    const int tid   = threadIdx.x;
    const int wq    = tid & 15;        // quad index within row (0..15)
    const int rbase = tid >> 4;        // 0..15; rows rbase + {0,16,32,48}

    const int bc = blockIdx.x;         // fused (b, c) plane index
    const int c  = bc - (bc / SH_C) * SH_C;
    const int g  = c >> 5;             // cpg = 32

    const long plane = (long)bc * (SH_H * SH_W);
    float4* __restrict__ dstp = reinterpret_cast<float4*>(out + plane) + wq;

    const float4 zero = make_float4(0.f, 0.f, 0.f, 0.f);

    if (g >= 8) {                      // zero group (channels 256..287)
#pragma unroll
        for (int i = 0; i < 4; ++i) {
            const int h = rbase + (i << 4);
            __stcs(dstp + h * (SH_W / 4), zero);
        }
        return;
    }

    const int dh = c_dh[g];
    const int dw = c_dw[g];

    const float4* __restrict__ srcp = reinterpret_cast<const float4*>(x + plane) + wq;

    // Issue all 4 aligned loads first (MLP=4). OOB source rows -> zero quad.
    float4 q[4];
#pragma unroll
    for (int i = 0; i < 4; ++i) {
        const int hs = rbase + (i << 4) + dh;
        q[i] = ((unsigned)hs < SH_H) ? __ldcs(srcp + hs * (SH_W / 4)) : zero;
    }

    if (dw == 0) {
#pragma unroll
        for (int i = 0; i < 4; ++i) {
            const int h = rbase + (i << 4);
            __stcs(dstp + h * (SH_W / 4), q[i]);
        }
    } else if (dw > 0) {
        // out quad = {q.y, q.z, q.w, next_lane.q.x}; wq==15 -> last elem = 0
#pragma unroll
        for (int i = 0; i < 4; ++i) {
            float nx = __shfl_down_sync(0xffffffffu, q[i].x, 1);
            if (wq == 15) nx = 0.f;
            const int h = rbase + (i << 4);
            __stcs(dstp + h * (SH_W / 4), make_float4(q[i].y, q[i].z, q[i].w, nx));
        }
    } else {
        // out quad = {prev_lane.q.w, q.x, q.y, q.z}; wq==0 -> first elem = 0
#pragma unroll
        for (int i = 0; i < 4; ++i) {
            float pw = __shfl_up_sync(0xffffffffu, q[i].w, 1);
            if (wq == 0) pw = 0.f;
            const int h = rbase + (i << 4);
            __stcs(dstp + h * (SH_W / 4), make_float4(pw, q[i].x, q[i].y, q[i].z));
        }
    }
}

extern "C" void kernel_launch(void* const* d_in, const int* in_sizes, int n_in,
                              void* d_out, int out_size) {
    const float* x = (const float*)d_in[0];
    float* out = (float*)d_out;
    const int grid = 32 * SH_C;   // one block per (b, c) plane
    shift_kernel<<<grid, 256>>>(x, out);
}